// round 1
// baseline (speedup 1.0000x reference)
#include <cuda_runtime.h>
#include <math.h>

#define D 4096
#define D4 1024
#define EPSF 1e-5f
#define EPS_VARF 1e-4f

// ---------------- device scratch (static; no allocations) ----------------
__device__ __align__(16) float  g_mean_in[D];
__device__ __align__(16) float  g_inv_in[D];
__device__ __align__(16) float  g_mean_out[D];
__device__ __align__(16) float  g_inv_out[D];
__device__ __align__(16) float  g_eman[D];
__device__ __align__(16) float  g_mask[D];
__device__ __align__(16) double g_novel[D];
__device__ float g_scal[6]; // tau, beta_up, beta_dn, gamma, beta_out, gamma_out

// ---------------- fast math helpers ----------------
__device__ __forceinline__ float tanh_fast(float x) {
    float y;
    asm("tanh.approx.f32 %0, %1;" : "=f"(y) : "f"(x));
    return y;
}

__device__ __forceinline__ float gelu_f(float x) {
    // 0.5*x*(1+tanh(sqrt(2/pi)*(x+0.044715*x^3)))
    float x3 = x * x * x;
    float t  = tanh_fast(0.7978845608028654f * (x + 0.044715f * x3));
    return 0.5f * x * (1.0f + t);
}

// ---------------- prep: channel constants, scalars, zero accumulators ----------------
__global__ void prep_kernel(const float* __restrict__ ema_mean,
                            const float* __restrict__ ema_sq,
                            const float* __restrict__ ema_out_mean,
                            const float* __restrict__ ema_out_sq,
                            const float* __restrict__ ema_out_dir,
                            const float* __restrict__ log_tau,
                            const float* __restrict__ log_beta_up,
                            const float* __restrict__ log_beta_dn,
                            const float* __restrict__ log_gamma,
                            const float* __restrict__ log_beta_out,
                            const float* __restrict__ log_gamma_out)
{
    __shared__ float red[8];
    __shared__ float s_invn;
    int t = threadIdx.x; // 256 threads

    // norm of ema_out_dir
    float s = 0.f;
    for (int c = t; c < D; c += 256) { float v = ema_out_dir[c]; s += v * v; }
    #pragma unroll
    for (int o = 16; o > 0; o >>= 1) s += __shfl_xor_sync(0xffffffffu, s, o);
    if ((t & 31) == 0) red[t >> 5] = s;
    __syncthreads();
    if (t == 0) {
        float tot = 0.f;
        #pragma unroll
        for (int i = 0; i < 8; i++) tot += red[i];
        s_invn = 1.0f / fmaxf(sqrtf(tot), 1e-12f);
        // scalars (softplus = log1p(exp(x)); args are O(1), numerically fine)
        g_scal[0] = expf(log_tau[0]);
        g_scal[1] = log1pf(expf(log_beta_up[0]));
        g_scal[2] = log1pf(expf(log_beta_dn[0]));
        g_scal[3] = log1pf(expf(log_gamma[0]));
        g_scal[4] = log1pf(expf(log_beta_out[0]));
        g_scal[5] = log1pf(expf(log_gamma_out[0]));
    }
    __syncthreads();
    float invn = s_invn;

    for (int c = t; c < D; c += 256) {
        float m   = ema_mean[c];
        float var = fmaxf(ema_sq[c] - m * m, EPS_VARF);
        g_mean_in[c] = m;
        g_inv_in[c]  = 1.0f / (sqrtf(var) + EPSF);
        float mo   = ema_out_mean[c];
        float varo = fmaxf(ema_out_sq[c] - mo * mo, EPS_VARF);
        g_mean_out[c] = mo;
        g_inv_out[c]  = 1.0f / (sqrtf(varo) + EPSF);
        g_eman[c]  = ema_out_dir[c] * invn;
        g_novel[c] = 0.0;
    }
}

// ---------------- novelty reduction: per-channel sum of |z_in| ----------------
// grid: (4, rows/64), block: 256 threads. Thread owns 4 channels (one float4
// column group), accumulates 64 rows: fp32 8-row partials -> fp64 accumulator.
__global__ void __launch_bounds__(256) novel_kernel(const float4* __restrict__ x4, int rows)
{
    int c4 = blockIdx.x * 256 + threadIdx.x; // float4 column index 0..1023
    int r0 = blockIdx.y * 64;
    if (r0 >= rows) return;
    int nr = rows - r0; if (nr > 64) nr = 64;

    const float4 m  = *(const float4*)&g_mean_in[c4 * 4];
    const float4 iv = *(const float4*)&g_inv_in[c4 * 4];

    double a0 = 0.0, a1 = 0.0, a2 = 0.0, a3 = 0.0;
    const float4* p = x4 + (size_t)r0 * D4 + c4;

    int r = 0;
    for (; r + 8 <= nr; r += 8) {
        float p0 = 0.f, p1 = 0.f, p2 = 0.f, p3 = 0.f;
        #pragma unroll
        for (int i = 0; i < 8; i++) {
            float4 v = p[(size_t)(r + i) * D4];
            p0 += fabsf(v.x - m.x) * iv.x;
            p1 += fabsf(v.y - m.y) * iv.y;
            p2 += fabsf(v.z - m.z) * iv.z;
            p3 += fabsf(v.w - m.w) * iv.w;
        }
        a0 += (double)p0; a1 += (double)p1; a2 += (double)p2; a3 += (double)p3;
    }
    for (; r < nr; r++) {
        float4 v = p[(size_t)r * D4];
        a0 += (double)(fabsf(v.x - m.x) * iv.x);
        a1 += (double)(fabsf(v.y - m.y) * iv.y);
        a2 += (double)(fabsf(v.z - m.z) * iv.z);
        a3 += (double)(fabsf(v.w - m.w) * iv.w);
    }

    atomicAdd(&g_novel[c4 * 4 + 0], a0);
    atomicAdd(&g_novel[c4 * 4 + 1], a1);
    atomicAdd(&g_novel[c4 * 4 + 2], a2);
    atomicAdd(&g_novel[c4 * 4 + 3], a3);
}

// ---------------- top-k hard mask via exact rank (matches jax.lax.top_k ties) ----------------
// grid: 256 blocks x 512 threads. One warp per channel; ballot-count over smem.
__global__ void __launch_bounds__(512) mask_kernel(const int* __restrict__ kptr)
{
    __shared__ double s[D];
    int t = threadIdx.x;
    for (int c = t; c < D; c += 512) s[c] = g_novel[c];
    __syncthreads();

    int k = kptr[0];
    if (k < 1 || k > D) {              // defensive: k delivered as float bits?
        float kf = __int_as_float(k);
        if (kf >= 1.0f && kf <= (float)D) k = (int)kf;
        else if (k < 1) k = 1;
        else k = D;
    }

    int w = t >> 5, lane = t & 31;
    int d = blockIdx.x * 16 + w;       // 256*16 = 4096 channels
    double sd = s[d];
    int cnt = 0;
    #pragma unroll 4
    for (int jj = 0; jj < D / 32; jj++) {
        int j = jj * 32 + lane;
        double v = s[j];
        bool p = (v > sd) || (v == sd && j < d);
        cnt += __popc(__ballot_sync(0xffffffffu, p));
    }
    if (lane == 0) g_mask[d] = (cnt < k) ? 1.0f : 0.0f;
}

// ---------------- fused per-row apply ----------------
__device__ __forceinline__ float apply_one(float x, float o,
                                           float mi, float ii, float mo, float io,
                                           float mk, float gc,
                                           float bu, float bd, float gm,
                                           float bo, float go)
{
    float zi = (x - mi) * ii;
    float zo = (o - mo) * io;
    float ti = tanh_fast(gm * zi);
    // 1 + bu*relu(t) - bd*relu(-t)  ==  1 + bu*max(t,0) + bd*min(t,0)
    float gin = 1.0f + bu * fmaxf(ti, 0.0f) + bd * fminf(ti, 0.0f);
    gin = fminf(fmaxf(gin, 0.05f), 8.0f);
    float gout = 1.0f + bo * tanh_fast(go * zo);
    gout = fminf(fmaxf(gout, 0.1f), 5.0f);
    float g = gin * gout * gc;
    // out * (g*mask + (1-mask)) = out * (1 + mask*(g-1))
    return o * (1.0f + mk * (g - 1.0f));
}

__global__ void __launch_bounds__(512) apply_kernel(const float4* __restrict__ x4,
                                                    float4* __restrict__ y4)
{
    __shared__ float redA[16], redB[16];
    __shared__ float s_gc;
    int row = blockIdx.x;
    int t = threadIdx.x;

    const float4* xp = x4 + (size_t)row * D4;
    float4 xa = xp[t];
    float4 xb = xp[t + 512];

    float4 oa, ob;
    oa.x = gelu_f(xa.x); oa.y = gelu_f(xa.y); oa.z = gelu_f(xa.z); oa.w = gelu_f(xa.w);
    ob.x = gelu_f(xb.x); ob.y = gelu_f(xb.y); ob.z = gelu_f(xb.z); ob.w = gelu_f(xb.w);

    float4 ea = *(const float4*)&g_eman[t * 4];
    float4 eb = *(const float4*)&g_eman[(t + 512) * 4];

    float s2 = oa.x * oa.x + oa.y * oa.y + oa.z * oa.z + oa.w * oa.w
             + ob.x * ob.x + ob.y * ob.y + ob.z * ob.z + ob.w * ob.w;
    float sd = oa.x * ea.x + oa.y * ea.y + oa.z * ea.z + oa.w * ea.w
             + ob.x * eb.x + ob.y * eb.y + ob.z * eb.z + ob.w * eb.w;

    #pragma unroll
    for (int o = 16; o > 0; o >>= 1) {
        s2 += __shfl_xor_sync(0xffffffffu, s2, o);
        sd += __shfl_xor_sync(0xffffffffu, sd, o);
    }
    int w = t >> 5, lane = t & 31;
    if (lane == 0) { redA[w] = s2; redB[w] = sd; }
    __syncthreads();
    if (t == 0) {
        float S2 = 0.f, SD = 0.f;
        #pragma unroll
        for (int i = 0; i < 16; i++) { S2 += redA[i]; SD += redB[i]; }
        float nrm = fmaxf(sqrtf(S2), 1e-12f);
        float cs = SD / nrm;
        cs = fminf(fmaxf(cs, -1.0f), 1.0f);
        s_gc = expf(-g_scal[0] * cs);
    }
    __syncthreads();

    float gc = s_gc;
    float bu = g_scal[1], bd = g_scal[2], gm = g_scal[3];
    float bo = g_scal[4], go = g_scal[5];

    // group a
    {
        int j = t;
        float4 mi = *(const float4*)&g_mean_in[j * 4];
        float4 ii = *(const float4*)&g_inv_in[j * 4];
        float4 mo = *(const float4*)&g_mean_out[j * 4];
        float4 io = *(const float4*)&g_inv_out[j * 4];
        float4 mk = *(const float4*)&g_mask[j * 4];
        float4 r;
        r.x = apply_one(xa.x, oa.x, mi.x, ii.x, mo.x, io.x, mk.x, gc, bu, bd, gm, bo, go);
        r.y = apply_one(xa.y, oa.y, mi.y, ii.y, mo.y, io.y, mk.y, gc, bu, bd, gm, bo, go);
        r.z = apply_one(xa.z, oa.z, mi.z, ii.z, mo.z, io.z, mk.z, gc, bu, bd, gm, bo, go);
        r.w = apply_one(xa.w, oa.w, mi.w, ii.w, mo.w, io.w, mk.w, gc, bu, bd, gm, bo, go);
        (y4 + (size_t)row * D4)[t] = r;
    }
    // group b
    {
        int j = t + 512;
        float4 mi = *(const float4*)&g_mean_in[j * 4];
        float4 ii = *(const float4*)&g_inv_in[j * 4];
        float4 mo = *(const float4*)&g_mean_out[j * 4];
        float4 io = *(const float4*)&g_inv_out[j * 4];
        float4 mk = *(const float4*)&g_mask[j * 4];
        float4 r;
        r.x = apply_one(xb.x, ob.x, mi.x, ii.x, mo.x, io.x, mk.x, gc, bu, bd, gm, bo, go);
        r.y = apply_one(xb.y, ob.y, mi.y, ii.y, mo.y, io.y, mk.y, gc, bu, bd, gm, bo, go);
        r.z = apply_one(xb.z, ob.z, mi.z, ii.z, mo.z, io.z, mk.z, gc, bu, bd, gm, bo, go);
        r.w = apply_one(xb.w, ob.w, mi.w, ii.w, mo.w, io.w, mk.w, gc, bu, bd, gm, bo, go);
        (y4 + (size_t)row * D4)[t + 512] = r;
    }
}

// ---------------- launch ----------------
extern "C" void kernel_launch(void* const* d_in, const int* in_sizes, int n_in,
                              void* d_out, int out_size)
{
    const float* x             = (const float*)d_in[0];
    // d_in[1] logit_decay: unused in forward
    const float* log_tau       = (const float*)d_in[2];
    const float* log_beta_up   = (const float*)d_in[3];
    const float* log_beta_dn   = (const float*)d_in[4];
    const float* log_gamma     = (const float*)d_in[5];
    const float* log_beta_out  = (const float*)d_in[6];
    const float* log_gamma_out = (const float*)d_in[7];
    // d_in[8] log_temperature: cancels in forward (straight-through)
    const float* ema_mean      = (const float*)d_in[9];
    const float* ema_sq        = (const float*)d_in[10];
    const float* ema_out_mean  = (const float*)d_in[11];
    const float* ema_out_sq    = (const float*)d_in[12];
    const float* ema_out_dir   = (const float*)d_in[13];
    const int*   kptr          = (const int*)d_in[14];

    int rows = in_sizes[0] / D; // 8192 for (4, 2048, 4096)

    prep_kernel<<<1, 256>>>(ema_mean, ema_sq, ema_out_mean, ema_out_sq, ema_out_dir,
                            log_tau, log_beta_up, log_beta_dn, log_gamma,
                            log_beta_out, log_gamma_out);

    dim3 ng(4, (rows + 63) / 64);
    novel_kernel<<<ng, 256>>>((const float4*)x, rows);

    mask_kernel<<<256, 512>>>(kptr);

    apply_kernel<<<rows, 512>>>((const float4*)x, (float4*)d_out);
}